// round 15
// baseline (speedup 1.0000x reference)
#include <cuda_runtime.h>
#include <cuda_bf16.h>
#include <math.h>
#include <stdint.h>

#define EMBED 128
#define HHID  512
#define MAXN  50000
#define MAXM  50000
#define MAXE  400000

// ---------------------------------------------------------------------------
// Scratch
// ---------------------------------------------------------------------------
__device__ __align__(16) float g_hs[MAXN * HHID];
__device__ __align__(16) float g_ht[MAXM * HHID];
__device__ __align__(16) float g_ms[MAXN * EMBED];
__device__ __align__(16) float g_agg[MAXM * EMBED];
__device__ int g_counts[MAXM];
__device__ int g_cursor[MAXM];
__device__ int g_offsets[MAXM + 1];
__device__ int g_sorted_src[MAXE];
__device__ __align__(16) __nv_bfloat16 g_wimg_src[5 * 32768];  // Ws (4 blocks) + Wm (1)
__device__ __align__(16) __nv_bfloat16 g_wimg_t[4 * 32768];    // Wt
__device__ __align__(16) __nv_bfloat16 g_wimg_o[32768];        // Wo

// ---------------------------------------------------------------------------
// helpers
// ---------------------------------------------------------------------------
__device__ __forceinline__ uint32_t smem_u32(const void* p) {
    uint32_t a;
    asm("{ .reg .u64 t; cvta.to.shared.u64 t, %1; cvt.u32.u64 %0, t; }" : "=r"(a) : "l"(p));
    return a;
}
__device__ __forceinline__ void ldsm_x4(uint32_t& r0, uint32_t& r1, uint32_t& r2, uint32_t& r3,
                                        uint32_t addr) {
    asm volatile("ldmatrix.sync.aligned.m8n8.x4.shared.b16 {%0,%1,%2,%3}, [%4];"
                 : "=r"(r0), "=r"(r1), "=r"(r2), "=r"(r3) : "r"(addr));
}
__device__ __forceinline__ void mma_bf16(float* d, const uint32_t* a, uint32_t b0, uint32_t b1) {
    asm volatile("mma.sync.aligned.m16n8k16.row.col.f32.bf16.bf16.f32 "
                 "{%0,%1,%2,%3}, {%4,%5,%6,%7}, {%8,%9}, {%0,%1,%2,%3};"
                 : "+f"(d[0]), "+f"(d[1]), "+f"(d[2]), "+f"(d[3])
                 : "r"(a[0]), "r"(a[1]), "r"(a[2]), "r"(a[3]), "r"(b0), "r"(b1));
}
__device__ __forceinline__ float gelu_fast(float x) {
    float z  = 0.70710678118654752440f * x;
    float az = fabsf(z);
    float t  = __fdividef(1.0f, fmaf(0.3275911f, az, 1.0f));
    float w  = fmaf(1.061405429f, t, -1.453152027f);
    w = fmaf(w, t, 1.421413741f);
    w = fmaf(w, t, -0.284496736f);
    w = fmaf(w, t, 0.254829592f);
    w = w * t;
    float e = __expf(-az * az);
    float erf_az = fmaf(-w, e, 1.0f);
    float erf_z  = copysignf(erf_az, z);
    return 0.5f * x * (1.0f + erf_z);
}
// per-edge logit partial for this lane (4 dims)
__device__ __forceinline__ float logit_part(float4 hv, float4 htv, float4 aw) {
    float x0 = gelu_fast(hv.x + htv.x);
    float x1 = gelu_fast(hv.y + htv.y);
    float x2 = gelu_fast(hv.z + htv.z);
    float x3 = gelu_fast(hv.w + htv.w);
    return fmaf(x0, aw.x, fmaf(x1, aw.y, fmaf(x2, aw.z, x3 * aw.w)));
}

// ---------------------------------------------------------------------------
// weight conversion + counter zeroing (one launch)
// ---------------------------------------------------------------------------
__device__ __forceinline__ void wconv_one(const float* __restrict__ W, int idx, int ncols,
                                          __nv_bfloat16* __restrict__ imgbase) {
    int k = idx / ncols, c = idx - k * ncols;
    int nb = c >> 7, n = c & 127;
    float x = W[idx];
    __nv_bfloat16 h = __float2bfloat16(x);
    __nv_bfloat16 l = __float2bfloat16(x - __bfloat162float(h));
    __nv_bfloat16* base = imgbase + (size_t)nb * 32768;
    base[n * 128 + k] = h;
    base[16384 + n * 128 + k] = l;
}
__global__ void wconv4z_kernel(const float* __restrict__ Ws, const float* __restrict__ Wm,
                               const float* __restrict__ Wt, const float* __restrict__ Wo,
                               __nv_bfloat16* __restrict__ img_src,
                               __nv_bfloat16* __restrict__ img_t,
                               __nv_bfloat16* __restrict__ img_o,
                               int* __restrict__ counts, int* __restrict__ cursor, int M) {
    int i = blockIdx.x * 256 + threadIdx.x;
    if (i < M) { counts[i] = 0; cursor[i] = 0; }
    if (i < 65536) {
        wconv_one(Ws, i, 512, img_src);
    } else if (i < 81920) {
        wconv_one(Wm, i - 65536, 128, img_src + 4 * 32768);
    } else if (i < 147456) {
        wconv_one(Wt, i - 81920, 512, img_t);
    } else if (i < 163840) {
        wconv_one(Wo, i - 147456, 128, img_o);
    }
}

// ---------------------------------------------------------------------------
// Persistent fused HMMA GEMM (unchanged from R13 — proven)
// ---------------------------------------------------------------------------
#define SMS 136
#define SM_TILE (128 * SMS)
#define RAW_BYTES 65536
#define PERSIST_SMEM (RAW_BYTES + 4 * SM_TILE * 2)

__device__ __forceinline__ void prefetch_a(const float* __restrict__ A, int row0, int rows,
                                           int tid, uint32_t sraw) {
    #pragma unroll
    for (int it = 0; it < 16; it++) {
        int idx = tid + it * 256;
        int r = idx >> 5, c4 = idx & 31;
        int gr = row0 + r;
        if (gr >= rows) gr = rows - 1;
        const float* src = A + (size_t)gr * 128 + c4 * 4;
        asm volatile("cp.async.ca.shared.global [%0], [%1], 16;"
                     :: "r"(sraw + (uint32_t)idx * 16), "l"(src));
    }
}

__global__ void __launch_bounds__(256, 1)
tc_gemm_persist(const float* __restrict__ Asrc, const float* __restrict__ Atgt,
                const float* __restrict__ Aagg,
                const __nv_bfloat16* __restrict__ img_src,
                const __nv_bfloat16* __restrict__ img_t,
                const __nv_bfloat16* __restrict__ img_o,
                const float* __restrict__ bs, const float* __restrict__ bm,
                const float* __restrict__ bt, const float* __restrict__ bo,
                float* __restrict__ hs, float* __restrict__ msp, float* __restrict__ ht,
                float* __restrict__ outp,
                int N, int M, int jobbase) {
    extern __shared__ __align__(16) char smraw[];
    float* sRawF = (float*)smraw;
    __nv_bfloat16* sAh = (__nv_bfloat16*)(smraw + RAW_BYTES);
    __nv_bfloat16* sAl = sAh + SM_TILE;
    __nv_bfloat16* sBh = sAl + SM_TILE;
    __nv_bfloat16* sBl = sBh + SM_TILE;

    int tid = threadIdx.x, wid = tid >> 5, lane = tid & 31;
    int job = jobbase + blockIdx.y;

    const float* A; const __nv_bfloat16* Bimg; const float* bias;
    float* C; int ncols, col0, rows;
    if (job < 4)      { A = Asrc; rows = N; Bimg = img_src + (size_t)job * 32768;
                        bias = bs; C = hs;  ncols = 512; col0 = job * 128; }
    else if (job == 4){ A = Asrc; rows = N; Bimg = img_src + 4ull * 32768;
                        bias = bm; C = msp; ncols = 128; col0 = 0; }
    else if (job < 9) { A = Atgt; rows = M; Bimg = img_t + (size_t)(job - 5) * 32768;
                        bias = bt; C = ht;  ncols = 512; col0 = (job - 5) * 128; }
    else              { A = Aagg; rows = M; Bimg = img_o;
                        bias = bo; C = outp; ncols = 128; col0 = 0; }

    int nxb = (rows + 127) >> 7;
    uint32_t sraw = smem_u32(sRawF);

    {
        const uint4* src = (const uint4*)Bimg;
        for (int idx = tid; idx < 2048; idx += 256) {
            int n = idx >> 4, k8 = (idx & 15);
            uint4 vh = src[idx];
            uint4 vl = src[2048 + idx];
            *(uint4*)(sBh + n * SMS + k8 * 8) = vh;
            *(uint4*)(sBl + n * SMS + k8 * 8) = vl;
        }
    }

    int xb0 = blockIdx.x;
    if (xb0 < nxb) prefetch_a(A, xb0 << 7, rows, tid, sraw);
    asm volatile("cp.async.commit_group;" ::: "memory");
    __syncthreads();

    int wm = (wid & 3) * 32;
    int wn = (wid >> 2) * 64;
    uint32_t a_base_h = smem_u32(sAh) + (((wm + (lane & 15)) * SMS + ((lane >> 4) << 3)) << 1);
    uint32_t a_base_l = a_base_h + (uint32_t)(SM_TILE << 1);
    uint32_t b_row = (uint32_t)(wn + ((lane & 16) >> 1) + (lane & 7));
    uint32_t b_base_h = smem_u32(sBh) + ((b_row * SMS + (lane & 8)) << 1);
    uint32_t b_base_l = b_base_h + (uint32_t)(SM_TILE << 1);

    for (int xb = xb0; xb < nxb; xb += gridDim.x) {
        int row0 = xb << 7;
        asm volatile("cp.async.wait_group 0;" ::: "memory");
        __syncthreads();

        #pragma unroll
        for (int it = 0; it < 16; it++) {
            int idx = tid + it * 256;
            int r = idx >> 5, k0 = (idx & 31) * 4;
            float4 v = *(const float4*)(sRawF + idx * 4);
            uint32_t h01, h23;
            asm("cvt.rn.satfinite.bf16x2.f32 %0, %1, %2;" : "=r"(h01) : "f"(v.y), "f"(v.x));
            asm("cvt.rn.satfinite.bf16x2.f32 %0, %1, %2;" : "=r"(h23) : "f"(v.w), "f"(v.z));
            float r0f = v.x - __uint_as_float(h01 << 16);
            float r1f = v.y - __uint_as_float(h01 & 0xffff0000u);
            float r2f = v.z - __uint_as_float(h23 << 16);
            float r3f = v.w - __uint_as_float(h23 & 0xffff0000u);
            uint32_t l01, l23;
            asm("cvt.rn.satfinite.bf16x2.f32 %0, %1, %2;" : "=r"(l01) : "f"(r1f), "f"(r0f));
            asm("cvt.rn.satfinite.bf16x2.f32 %0, %1, %2;" : "=r"(l23) : "f"(r3f), "f"(r2f));
            *(uint2*)(sAh + r * SMS + k0) = make_uint2(h01, h23);
            *(uint2*)(sAl + r * SMS + k0) = make_uint2(l01, l23);
        }
        __syncthreads();

        int xn = xb + gridDim.x;
        if (xn < nxb) prefetch_a(A, xn << 7, rows, tid, sraw);
        asm volatile("cp.async.commit_group;" ::: "memory");

        float acc[2][8][4];
        #pragma unroll
        for (int i = 0; i < 2; i++)
            #pragma unroll
            for (int j = 0; j < 8; j++)
                #pragma unroll
                for (int q = 0; q < 4; q++) acc[i][j][q] = 0.f;

        #pragma unroll
        for (int ks = 0; ks < 8; ks++) {
            uint32_t koff = (uint32_t)(ks * 16 * 2);
            uint32_t ah[2][4], al[2][4];
            #pragma unroll
            for (int mt = 0; mt < 2; mt++) {
                uint32_t off = koff + (uint32_t)((mt * 16 * SMS) << 1);
                ldsm_x4(ah[mt][0], ah[mt][1], ah[mt][2], ah[mt][3], a_base_h + off);
                ldsm_x4(al[mt][0], al[mt][1], al[mt][2], al[mt][3], a_base_l + off);
            }
            #pragma unroll
            for (int np = 0; np < 4; np++) {
                uint32_t off = koff + (uint32_t)((np * 16 * SMS) << 1);
                uint32_t bh[4], bl[4];
                ldsm_x4(bh[0], bh[1], bh[2], bh[3], b_base_h + off);
                ldsm_x4(bl[0], bl[1], bl[2], bl[3], b_base_l + off);
                #pragma unroll
                for (int mt = 0; mt < 2; mt++) {
                    mma_bf16(acc[mt][np * 2 + 0], ah[mt], bh[0], bh[1]);
                    mma_bf16(acc[mt][np * 2 + 1], ah[mt], bh[2], bh[3]);
                    mma_bf16(acc[mt][np * 2 + 0], ah[mt], bl[0], bl[1]);
                    mma_bf16(acc[mt][np * 2 + 1], ah[mt], bl[2], bl[3]);
                    mma_bf16(acc[mt][np * 2 + 0], al[mt], bh[0], bh[1]);
                    mma_bf16(acc[mt][np * 2 + 1], al[mt], bh[2], bh[3]);
                }
            }
        }

        int g = lane >> 2, tg = lane & 3;
        #pragma unroll
        for (int mt = 0; mt < 2; mt++) {
            int r_lo = row0 + wm + mt * 16 + g;
            int r_hi = r_lo + 8;
            #pragma unroll
            for (int nt = 0; nt < 8; nt++) {
                int gc = col0 + wn + nt * 8 + tg * 2;
                float b0 = bias[gc], b1 = bias[gc + 1];
                if (r_lo < rows) {
                    float2 o = make_float2(acc[mt][nt][0] + b0, acc[mt][nt][1] + b1);
                    *(float2*)(C + (size_t)r_lo * ncols + gc) = o;
                }
                if (r_hi < rows) {
                    float2 o = make_float2(acc[mt][nt][2] + b0, acc[mt][nt][3] + b1);
                    *(float2*)(C + (size_t)r_hi * ncols + gc) = o;
                }
            }
        }
    }
}

// ---------------------------------------------------------------------------
// CSR build
// ---------------------------------------------------------------------------
__global__ void hist_kernel(const int* __restrict__ etgt, int* __restrict__ counts, int E) {
    int i = blockIdx.x * blockDim.x + threadIdx.x;
    if (i < E) atomicAdd(&counts[etgt[i]], 1);
}
__global__ void scan_kernel(const int* __restrict__ counts, int* __restrict__ offsets, int M) {
    __shared__ int wsum[32];
    int t = threadIdx.x;
    int chunk = (M + 1023) >> 10;
    int b0 = t * chunk, b1 = b0 + chunk;
    if (b0 > M) b0 = M;
    if (b1 > M) b1 = M;
    int s = 0;
    for (int i = b0; i < b1; i++) s += counts[i];
    int lane = t & 31, w = t >> 5;
    int v = s;
    #pragma unroll
    for (int o = 1; o < 32; o <<= 1) { int x = __shfl_up_sync(0xffffffffu, v, o); if (lane >= o) v += x; }
    if (lane == 31) wsum[w] = v;
    __syncthreads();
    if (w == 0) {
        int x = wsum[lane];
        #pragma unroll
        for (int o = 1; o < 32; o <<= 1) { int y = __shfl_up_sync(0xffffffffu, x, o); if (lane >= o) x += y; }
        wsum[lane] = x;
    }
    __syncthreads();
    int run = v - s + (w > 0 ? wsum[w - 1] : 0);
    for (int i = b0; i < b1; i++) { offsets[i] = run; run += counts[i]; }
    if (t == 1023) offsets[M] = run;
}
__global__ void scatter_kernel(const int* __restrict__ etgt, const int* __restrict__ esrc,
                               const int* __restrict__ offsets, int* __restrict__ cursor,
                               int* __restrict__ ssrc, int E) {
    int i = blockIdx.x * blockDim.x + threadIdx.x;
    if (i < E) {
        int tg = etgt[i];
        int pos = offsets[tg] + atomicAdd(&cursor[tg], 1);
        ssrc[pos] = esrc[i];
    }
}

// ---------------------------------------------------------------------------
// Edge attention v3: head-split, anchored softmax (no online recurrence),
// 4-edge batched with joint cross-edge reduction.
// ---------------------------------------------------------------------------
__global__ void __launch_bounds__(256)
edge_attn_kernel(const int* __restrict__ sorted_src,
                 const int* __restrict__ offsets,
                 const float4* __restrict__ hs4,
                 const float4* __restrict__ ht4,
                 const float* __restrict__ ms,
                 const float4* __restrict__ aw4,
                 float* __restrict__ agg,
                 int M) {
    int gw = (blockIdx.x * blockDim.x + threadIdx.x) >> 5;
    int lane = threadIdx.x & 31;
    int tgt = gw >> 2;
    int h = gw & 3;
    if (tgt >= M) return;
    int beg = offsets[tgt], end = offsets[tgt + 1];
    int fidx = h * 32 + lane;

    if (beg == end) { agg[(size_t)tgt * 128 + fidx] = 0.f; return; }

    float4 htv = ht4[(size_t)tgt * 128 + fidx];
    float4 aw = aw4[fidx];

    // ---- anchor edge (first): e = 1 ----
    int s0 = sorted_src[beg];
    float msg0 = ms[(size_t)s0 * 128 + fidx];
    float4 h0 = hs4[(size_t)s0 * 128 + fidx];
    float anchor = logit_part(h0, htv, aw);
    #pragma unroll
    for (int o = 16; o > 0; o >>= 1)
        anchor += __shfl_xor_sync(0xffffffffu, anchor, o);
    float d = 1.0f;
    float acc = msg0;

    int p = beg + 1;
    int q = lane >> 3;

    // ---- 4-edge batched mainloop ----
    for (; p + 3 < end; p += 4) {
        int sa = sorted_src[p + 0];
        int sb = sorted_src[p + 1];
        int sc = sorted_src[p + 2];
        int sd = sorted_src[p + 3];
        float ma = ms[(size_t)sa * 128 + fidx];
        float mb = ms[(size_t)sb * 128 + fidx];
        float mc = ms[(size_t)sc * 128 + fidx];
        float md = ms[(size_t)sd * 128 + fidx];
        float4 ha = hs4[(size_t)sa * 128 + fidx];
        float4 hb = hs4[(size_t)sb * 128 + fidx];
        float4 hc = hs4[(size_t)sc * 128 + fidx];
        float4 hd = hs4[(size_t)sd * 128 + fidx];

        float pa = logit_part(ha, htv, aw);
        float pb = logit_part(hb, htv, aw);
        float pc = logit_part(hc, htv, aw);
        float pd = logit_part(hd, htv, aw);

        // partial reduce each over bits {4,3}
        pa += __shfl_xor_sync(0xffffffffu, pa, 16);
        pb += __shfl_xor_sync(0xffffffffu, pb, 16);
        pc += __shfl_xor_sync(0xffffffffu, pc, 16);
        pd += __shfl_xor_sync(0xffffffffu, pd, 16);
        pa += __shfl_xor_sync(0xffffffffu, pa, 8);
        pb += __shfl_xor_sync(0xffffffffu, pb, 8);
        pc += __shfl_xor_sync(0xffffffffu, pc, 8);
        pd += __shfl_xor_sync(0xffffffffu, pd, 8);
        // each 8-lane group finishes one edge
        float v = (q == 0) ? pa : (q == 1) ? pb : (q == 2) ? pc : pd;
        v += __shfl_xor_sync(0xffffffffu, v, 4);
        v += __shfl_xor_sync(0xffffffffu, v, 2);
        v += __shfl_xor_sync(0xffffffffu, v, 1);
        // one exp per group, then broadcast the 4 e-values
        float e = __expf(v - anchor);
        float ea = __shfl_sync(0xffffffffu, e, 0);
        float eb = __shfl_sync(0xffffffffu, e, 8);
        float ec = __shfl_sync(0xffffffffu, e, 16);
        float ed = __shfl_sync(0xffffffffu, e, 24);

        d += (ea + eb) + (ec + ed);
        acc = fmaf(ma, ea, acc);
        acc = fmaf(mb, eb, acc);
        acc = fmaf(mc, ec, acc);
        acc = fmaf(md, ed, acc);
    }
    // ---- tail (1-3 edges) ----
    for (; p < end; p++) {
        int s = sorted_src[p];
        float msg = ms[(size_t)s * 128 + fidx];
        float4 hv = hs4[(size_t)s * 128 + fidx];
        float part = logit_part(hv, htv, aw);
        #pragma unroll
        for (int o = 16; o > 0; o >>= 1)
            part += __shfl_xor_sync(0xffffffffu, part, o);
        float e = __expf(part - anchor);
        d += e;
        acc = fmaf(msg, e, acc);
    }

    agg[(size_t)tgt * 128 + fidx] = acc * (1.0f / d);
}

// ---------------------------------------------------------------------------
// launch
// ---------------------------------------------------------------------------
extern "C" void kernel_launch(void* const* d_in, const int* in_sizes, int n_in,
                              void* d_out, int out_size) {
    const float* src_f = (const float*)d_in[0];
    const float* tgt_f = (const float*)d_in[1];
    const int*   etgt  = (const int*)d_in[2];
    const int*   esrc  = (const int*)d_in[3];
    const float* Ws    = (const float*)d_in[4];
    const float* bs    = (const float*)d_in[5];
    const float* Wt    = (const float*)d_in[6];
    const float* bt    = (const float*)d_in[7];
    const float* aw    = (const float*)d_in[8];
    const float* Wm    = (const float*)d_in[9];
    const float* bm    = (const float*)d_in[10];
    const float* Wo    = (const float*)d_in[11];
    const float* bo    = (const float*)d_in[12];
    float* out = (float*)d_out;

    int N = in_sizes[0] / EMBED;
    int M = in_sizes[1] / EMBED;
    int E = in_sizes[2];

    float *p_hs, *p_ht, *p_ms, *p_agg;
    int *p_counts, *p_cursor, *p_offsets, *p_ssrc;
    __nv_bfloat16 *p_wsrc, *p_wt, *p_wo;
    cudaGetSymbolAddress((void**)&p_hs, g_hs);
    cudaGetSymbolAddress((void**)&p_ht, g_ht);
    cudaGetSymbolAddress((void**)&p_ms, g_ms);
    cudaGetSymbolAddress((void**)&p_agg, g_agg);
    cudaGetSymbolAddress((void**)&p_counts, g_counts);
    cudaGetSymbolAddress((void**)&p_cursor, g_cursor);
    cudaGetSymbolAddress((void**)&p_offsets, g_offsets);
    cudaGetSymbolAddress((void**)&p_ssrc, g_sorted_src);
    cudaGetSymbolAddress((void**)&p_wsrc, g_wimg_src);
    cudaGetSymbolAddress((void**)&p_wt, g_wimg_t);
    cudaGetSymbolAddress((void**)&p_wo, g_wimg_o);

    cudaFuncSetAttribute(tc_gemm_persist,
                         cudaFuncAttributeMaxDynamicSharedMemorySize, PERSIST_SMEM);

    // 0: weight conversion + counter zeroing
    wconv4z_kernel<<<640, 256>>>(Ws, Wm, Wt, Wo, p_wsrc, p_wt, p_wo,
                                 p_counts, p_cursor, M);
    // 1-3: CSR build
    hist_kernel<<<(E + 255) / 256, 256>>>(etgt, p_counts, E);
    scan_kernel<<<1, 1024>>>(p_counts, p_offsets, M);
    scatter_kernel<<<(E + 255) / 256, 256>>>(etgt, esrc, p_offsets, p_cursor, p_ssrc, E);
    // 4: fused src+tgt GEMMs
    {
        dim3 g(16, 9);
        tc_gemm_persist<<<g, 256, PERSIST_SMEM>>>(src_f, tgt_f, p_agg,
                                                  p_wsrc, p_wt, p_wo,
                                                  bs, bm, bt, bo,
                                                  p_hs, p_ms, p_ht, out,
                                                  N, M, 0);
    }
    // 5: edge attention (capture slot)
    {
        int warps = M * 4;
        int blocks = (warps + 7) / 8;
        edge_attn_kernel<<<blocks, 256>>>(p_ssrc, p_offsets,
                                          (const float4*)p_hs, (const float4*)p_ht,
                                          p_ms, (const float4*)aw,
                                          p_agg, M);
    }
    // 6: output projection
    {
        dim3 g(148, 1);
        tc_gemm_persist<<<g, 256, PERSIST_SMEM>>>(src_f, tgt_f, p_agg,
                                                  p_wsrc, p_wt, p_wo,
                                                  bs, bm, bt, bo,
                                                  p_hs, p_ms, p_ht, out,
                                                  N, M, 9);
    }
}

// round 17
// speedup vs baseline: 1.0084x; 1.0084x over previous
#include <cuda_runtime.h>
#include <cuda_bf16.h>
#include <math.h>
#include <stdint.h>

#define EMBED 128
#define HHID  512
#define MAXN  50000
#define MAXM  50000
#define MAXE  400000

// ---------------------------------------------------------------------------
// Scratch
// ---------------------------------------------------------------------------
__device__ __align__(16) float g_hs[MAXN * HHID];
__device__ __align__(16) float g_ht[MAXM * HHID];
__device__ __align__(16) float g_ms[MAXN * EMBED];
__device__ __align__(16) float g_agg[MAXM * EMBED];
__device__ int g_counts[MAXM];
__device__ int g_cursor[MAXM];
__device__ int g_offsets[MAXM + 1];
__device__ int g_sorted_src[MAXE];
__device__ __align__(16) __nv_bfloat16 g_wimg_src[5 * 32768];  // Ws (4 blocks) + Wm (1)
__device__ __align__(16) __nv_bfloat16 g_wimg_t[4 * 32768];    // Wt
__device__ __align__(16) __nv_bfloat16 g_wimg_o[32768];        // Wo

// ---------------------------------------------------------------------------
// helpers
// ---------------------------------------------------------------------------
__device__ __forceinline__ uint32_t smem_u32(const void* p) {
    uint32_t a;
    asm("{ .reg .u64 t; cvta.to.shared.u64 t, %1; cvt.u32.u64 %0, t; }" : "=r"(a) : "l"(p));
    return a;
}
__device__ __forceinline__ void ldsm_x4(uint32_t& r0, uint32_t& r1, uint32_t& r2, uint32_t& r3,
                                        uint32_t addr) {
    asm volatile("ldmatrix.sync.aligned.m8n8.x4.shared.b16 {%0,%1,%2,%3}, [%4];"
                 : "=r"(r0), "=r"(r1), "=r"(r2), "=r"(r3) : "r"(addr));
}
__device__ __forceinline__ void mma_bf16(float* d, const uint32_t* a, uint32_t b0, uint32_t b1) {
    asm volatile("mma.sync.aligned.m16n8k16.row.col.f32.bf16.bf16.f32 "
                 "{%0,%1,%2,%3}, {%4,%5,%6,%7}, {%8,%9}, {%0,%1,%2,%3};"
                 : "+f"(d[0]), "+f"(d[1]), "+f"(d[2]), "+f"(d[3])
                 : "r"(a[0]), "r"(a[1]), "r"(a[2]), "r"(a[3]), "r"(b0), "r"(b1));
}
__device__ __forceinline__ float gelu_fast(float x) {
    float z  = 0.70710678118654752440f * x;
    float az = fabsf(z);
    float t  = __fdividef(1.0f, fmaf(0.3275911f, az, 1.0f));
    float w  = fmaf(1.061405429f, t, -1.453152027f);
    w = fmaf(w, t, 1.421413741f);
    w = fmaf(w, t, -0.284496736f);
    w = fmaf(w, t, 0.254829592f);
    w = w * t;
    float e = __expf(-az * az);
    float erf_az = fmaf(-w, e, 1.0f);
    float erf_z  = copysignf(erf_az, z);
    return 0.5f * x * (1.0f + erf_z);
}

// cache-policy steered loads (createpolicy + L2::cache_hint — base-ISA legal)
__device__ __forceinline__ uint64_t make_policy_evict_last() {
    uint64_t p;
    asm("createpolicy.fractional.L2::evict_last.b64 %0, 1.0;" : "=l"(p));
    return p;
}
__device__ __forceinline__ uint64_t make_policy_evict_first() {
    uint64_t p;
    asm("createpolicy.fractional.L2::evict_first.b64 %0, 1.0;" : "=l"(p));
    return p;
}
__device__ __forceinline__ float4 ldg_hint4(const float4* p, uint64_t pol) {
    float4 v;
    asm volatile("ld.global.nc.L2::cache_hint.v4.f32 {%0,%1,%2,%3}, [%4], %5;"
                 : "=f"(v.x), "=f"(v.y), "=f"(v.z), "=f"(v.w) : "l"(p), "l"(pol));
    return v;
}
__device__ __forceinline__ float ldg_hint1(const float* p, uint64_t pol) {
    float v;
    asm volatile("ld.global.nc.L2::cache_hint.f32 %0, [%1], %2;"
                 : "=f"(v) : "l"(p), "l"(pol));
    return v;
}
__device__ __forceinline__ void stg_stream1(float* p, float v) {
    asm volatile("st.global.cs.f32 [%0], %1;" :: "l"(p), "f"(v) : "memory");
}

// ---------------------------------------------------------------------------
// weight conversion + counter zeroing (one launch)
// ---------------------------------------------------------------------------
__device__ __forceinline__ void wconv_one(const float* __restrict__ W, int idx, int ncols,
                                          __nv_bfloat16* __restrict__ imgbase) {
    int k = idx / ncols, c = idx - k * ncols;
    int nb = c >> 7, n = c & 127;
    float x = W[idx];
    __nv_bfloat16 h = __float2bfloat16(x);
    __nv_bfloat16 l = __float2bfloat16(x - __bfloat162float(h));
    __nv_bfloat16* base = imgbase + (size_t)nb * 32768;
    base[n * 128 + k] = h;
    base[16384 + n * 128 + k] = l;
}
__global__ void wconv4z_kernel(const float* __restrict__ Ws, const float* __restrict__ Wm,
                               const float* __restrict__ Wt, const float* __restrict__ Wo,
                               __nv_bfloat16* __restrict__ img_src,
                               __nv_bfloat16* __restrict__ img_t,
                               __nv_bfloat16* __restrict__ img_o,
                               int* __restrict__ counts, int* __restrict__ cursor, int M) {
    int i = blockIdx.x * 256 + threadIdx.x;
    if (i < M) { counts[i] = 0; cursor[i] = 0; }
    if (i < 65536) {
        wconv_one(Ws, i, 512, img_src);
    } else if (i < 81920) {
        wconv_one(Wm, i - 65536, 128, img_src + 4 * 32768);
    } else if (i < 147456) {
        wconv_one(Wt, i - 81920, 512, img_t);
    } else if (i < 163840) {
        wconv_one(Wo, i - 147456, 128, img_o);
    }
}

// ---------------------------------------------------------------------------
// Persistent fused HMMA GEMM (unchanged — proven)
// ---------------------------------------------------------------------------
#define SMS 136
#define SM_TILE (128 * SMS)
#define RAW_BYTES 65536
#define PERSIST_SMEM (RAW_BYTES + 4 * SM_TILE * 2)

__device__ __forceinline__ void prefetch_a(const float* __restrict__ A, int row0, int rows,
                                           int tid, uint32_t sraw) {
    #pragma unroll
    for (int it = 0; it < 16; it++) {
        int idx = tid + it * 256;
        int r = idx >> 5, c4 = idx & 31;
        int gr = row0 + r;
        if (gr >= rows) gr = rows - 1;
        const float* src = A + (size_t)gr * 128 + c4 * 4;
        asm volatile("cp.async.ca.shared.global [%0], [%1], 16;"
                     :: "r"(sraw + (uint32_t)idx * 16), "l"(src));
    }
}

__global__ void __launch_bounds__(256, 1)
tc_gemm_persist(const float* __restrict__ Asrc, const float* __restrict__ Atgt,
                const float* __restrict__ Aagg,
                const __nv_bfloat16* __restrict__ img_src,
                const __nv_bfloat16* __restrict__ img_t,
                const __nv_bfloat16* __restrict__ img_o,
                const float* __restrict__ bs, const float* __restrict__ bm,
                const float* __restrict__ bt, const float* __restrict__ bo,
                float* __restrict__ hs, float* __restrict__ msp, float* __restrict__ ht,
                float* __restrict__ outp,
                int N, int M, int jobbase) {
    extern __shared__ __align__(16) char smraw[];
    float* sRawF = (float*)smraw;
    __nv_bfloat16* sAh = (__nv_bfloat16*)(smraw + RAW_BYTES);
    __nv_bfloat16* sAl = sAh + SM_TILE;
    __nv_bfloat16* sBh = sAl + SM_TILE;
    __nv_bfloat16* sBl = sBh + SM_TILE;

    int tid = threadIdx.x, wid = tid >> 5, lane = tid & 31;
    int job = jobbase + blockIdx.y;

    const float* A; const __nv_bfloat16* Bimg; const float* bias;
    float* C; int ncols, col0, rows;
    if (job < 4)      { A = Asrc; rows = N; Bimg = img_src + (size_t)job * 32768;
                        bias = bs; C = hs;  ncols = 512; col0 = job * 128; }
    else if (job == 4){ A = Asrc; rows = N; Bimg = img_src + 4ull * 32768;
                        bias = bm; C = msp; ncols = 128; col0 = 0; }
    else if (job < 9) { A = Atgt; rows = M; Bimg = img_t + (size_t)(job - 5) * 32768;
                        bias = bt; C = ht;  ncols = 512; col0 = (job - 5) * 128; }
    else              { A = Aagg; rows = M; Bimg = img_o;
                        bias = bo; C = outp; ncols = 128; col0 = 0; }

    int nxb = (rows + 127) >> 7;
    uint32_t sraw = smem_u32(sRawF);

    {
        const uint4* src = (const uint4*)Bimg;
        for (int idx = tid; idx < 2048; idx += 256) {
            int n = idx >> 4, k8 = (idx & 15);
            uint4 vh = src[idx];
            uint4 vl = src[2048 + idx];
            *(uint4*)(sBh + n * SMS + k8 * 8) = vh;
            *(uint4*)(sBl + n * SMS + k8 * 8) = vl;
        }
    }

    int xb0 = blockIdx.x;
    if (xb0 < nxb) prefetch_a(A, xb0 << 7, rows, tid, sraw);
    asm volatile("cp.async.commit_group;" ::: "memory");
    __syncthreads();

    int wm = (wid & 3) * 32;
    int wn = (wid >> 2) * 64;
    uint32_t a_base_h = smem_u32(sAh) + (((wm + (lane & 15)) * SMS + ((lane >> 4) << 3)) << 1);
    uint32_t a_base_l = a_base_h + (uint32_t)(SM_TILE << 1);
    uint32_t b_row = (uint32_t)(wn + ((lane & 16) >> 1) + (lane & 7));
    uint32_t b_base_h = smem_u32(sBh) + ((b_row * SMS + (lane & 8)) << 1);
    uint32_t b_base_l = b_base_h + (uint32_t)(SM_TILE << 1);

    for (int xb = xb0; xb < nxb; xb += gridDim.x) {
        int row0 = xb << 7;
        asm volatile("cp.async.wait_group 0;" ::: "memory");
        __syncthreads();

        #pragma unroll
        for (int it = 0; it < 16; it++) {
            int idx = tid + it * 256;
            int r = idx >> 5, k0 = (idx & 31) * 4;
            float4 v = *(const float4*)(sRawF + idx * 4);
            uint32_t h01, h23;
            asm("cvt.rn.satfinite.bf16x2.f32 %0, %1, %2;" : "=r"(h01) : "f"(v.y), "f"(v.x));
            asm("cvt.rn.satfinite.bf16x2.f32 %0, %1, %2;" : "=r"(h23) : "f"(v.w), "f"(v.z));
            float r0f = v.x - __uint_as_float(h01 << 16);
            float r1f = v.y - __uint_as_float(h01 & 0xffff0000u);
            float r2f = v.z - __uint_as_float(h23 << 16);
            float r3f = v.w - __uint_as_float(h23 & 0xffff0000u);
            uint32_t l01, l23;
            asm("cvt.rn.satfinite.bf16x2.f32 %0, %1, %2;" : "=r"(l01) : "f"(r1f), "f"(r0f));
            asm("cvt.rn.satfinite.bf16x2.f32 %0, %1, %2;" : "=r"(l23) : "f"(r3f), "f"(r2f));
            *(uint2*)(sAh + r * SMS + k0) = make_uint2(h01, h23);
            *(uint2*)(sAl + r * SMS + k0) = make_uint2(l01, l23);
        }
        __syncthreads();

        int xn = xb + gridDim.x;
        if (xn < nxb) prefetch_a(A, xn << 7, rows, tid, sraw);
        asm volatile("cp.async.commit_group;" ::: "memory");

        float acc[2][8][4];
        #pragma unroll
        for (int i = 0; i < 2; i++)
            #pragma unroll
            for (int j = 0; j < 8; j++)
                #pragma unroll
                for (int q = 0; q < 4; q++) acc[i][j][q] = 0.f;

        #pragma unroll
        for (int ks = 0; ks < 8; ks++) {
            uint32_t koff = (uint32_t)(ks * 16 * 2);
            uint32_t ah[2][4], al[2][4];
            #pragma unroll
            for (int mt = 0; mt < 2; mt++) {
                uint32_t off = koff + (uint32_t)((mt * 16 * SMS) << 1);
                ldsm_x4(ah[mt][0], ah[mt][1], ah[mt][2], ah[mt][3], a_base_h + off);
                ldsm_x4(al[mt][0], al[mt][1], al[mt][2], al[mt][3], a_base_l + off);
            }
            #pragma unroll
            for (int np = 0; np < 4; np++) {
                uint32_t off = koff + (uint32_t)((np * 16 * SMS) << 1);
                uint32_t bh[4], bl[4];
                ldsm_x4(bh[0], bh[1], bh[2], bh[3], b_base_h + off);
                ldsm_x4(bl[0], bl[1], bl[2], bl[3], b_base_l + off);
                #pragma unroll
                for (int mt = 0; mt < 2; mt++) {
                    mma_bf16(acc[mt][np * 2 + 0], ah[mt], bh[0], bh[1]);
                    mma_bf16(acc[mt][np * 2 + 1], ah[mt], bh[2], bh[3]);
                    mma_bf16(acc[mt][np * 2 + 0], ah[mt], bl[0], bl[1]);
                    mma_bf16(acc[mt][np * 2 + 1], ah[mt], bl[2], bl[3]);
                    mma_bf16(acc[mt][np * 2 + 0], al[mt], bh[0], bh[1]);
                    mma_bf16(acc[mt][np * 2 + 1], al[mt], bh[2], bh[3]);
                }
            }
        }

        int g = lane >> 2, tg = lane & 3;
        #pragma unroll
        for (int mt = 0; mt < 2; mt++) {
            int r_lo = row0 + wm + mt * 16 + g;
            int r_hi = r_lo + 8;
            #pragma unroll
            for (int nt = 0; nt < 8; nt++) {
                int gc = col0 + wn + nt * 8 + tg * 2;
                float b0 = bias[gc], b1 = bias[gc + 1];
                if (r_lo < rows) {
                    float2 o = make_float2(acc[mt][nt][0] + b0, acc[mt][nt][1] + b1);
                    *(float2*)(C + (size_t)r_lo * ncols + gc) = o;
                }
                if (r_hi < rows) {
                    float2 o = make_float2(acc[mt][nt][2] + b0, acc[mt][nt][3] + b1);
                    *(float2*)(C + (size_t)r_hi * ncols + gc) = o;
                }
            }
        }
    }
}

// ---------------------------------------------------------------------------
// CSR build
// ---------------------------------------------------------------------------
__global__ void hist_kernel(const int* __restrict__ etgt, int* __restrict__ counts, int E) {
    int i = blockIdx.x * blockDim.x + threadIdx.x;
    if (i < E) atomicAdd(&counts[etgt[i]], 1);
}
__global__ void scan_kernel(const int* __restrict__ counts, int* __restrict__ offsets, int M) {
    __shared__ int wsum[32];
    int t = threadIdx.x;
    int chunk = (M + 1023) >> 10;
    int b0 = t * chunk, b1 = b0 + chunk;
    if (b0 > M) b0 = M;
    if (b1 > M) b1 = M;
    int s = 0;
    for (int i = b0; i < b1; i++) s += counts[i];
    int lane = t & 31, w = t >> 5;
    int v = s;
    #pragma unroll
    for (int o = 1; o < 32; o <<= 1) { int x = __shfl_up_sync(0xffffffffu, v, o); if (lane >= o) v += x; }
    if (lane == 31) wsum[w] = v;
    __syncthreads();
    if (w == 0) {
        int x = wsum[lane];
        #pragma unroll
        for (int o = 1; o < 32; o <<= 1) { int y = __shfl_up_sync(0xffffffffu, x, o); if (lane >= o) x += y; }
        wsum[lane] = x;
    }
    __syncthreads();
    int run = v - s + (w > 0 ? wsum[w - 1] : 0);
    for (int i = b0; i < b1; i++) { offsets[i] = run; run += counts[i]; }
    if (t == 1023) offsets[M] = run;
}
__global__ void scatter_kernel(const int* __restrict__ etgt, const int* __restrict__ esrc,
                               const int* __restrict__ offsets, int* __restrict__ cursor,
                               int* __restrict__ ssrc, int E) {
    int i = blockIdx.x * blockDim.x + threadIdx.x;
    if (i < E) {
        int tg = etgt[i];
        int pos = offsets[tg] + atomicAdd(&cursor[tg], 1);
        ssrc[pos] = esrc[i];
    }
}

// ---------------------------------------------------------------------------
// Edge attention: head-split + 2-edge ILP (R13 structure) with L2 policy
// steering: hs/ms pinned (evict_last), ht streamed (evict_first), agg .cs.
// ---------------------------------------------------------------------------
__global__ void __launch_bounds__(256)
edge_attn_kernel(const int* __restrict__ sorted_src,
                 const int* __restrict__ offsets,
                 const float4* __restrict__ hs4,
                 const float4* __restrict__ ht4,
                 const float* __restrict__ ms,
                 const float4* __restrict__ aw4,
                 float* __restrict__ agg,
                 int M) {
    int gw = (blockIdx.x * blockDim.x + threadIdx.x) >> 5;
    int lane = threadIdx.x & 31;
    int tgt = gw >> 2;
    int h = gw & 3;
    if (tgt >= M) return;
    int beg = offsets[tgt], end = offsets[tgt + 1];

    uint64_t pol_keep = make_policy_evict_last();
    uint64_t pol_stream = make_policy_evict_first();

    int fidx = h * 32 + lane;
    float4 htv = ldg_hint4(ht4 + (size_t)tgt * 128 + fidx, pol_stream);
    float4 aw = aw4[fidx];

    float m = -3.4e38f;
    float d = 0.f;
    float acc = 0.f;

    int p = beg;
    for (; p + 1 < end; p += 2) {
        int s0 = sorted_src[p];
        int s1 = sorted_src[p + 1];
        float msg0 = ldg_hint1(ms + (size_t)s0 * 128 + fidx, pol_keep);
        float msg1 = ldg_hint1(ms + (size_t)s1 * 128 + fidx, pol_keep);
        float4 h0 = ldg_hint4(hs4 + (size_t)s0 * 128 + fidx, pol_keep);
        float4 h1 = ldg_hint4(hs4 + (size_t)s1 * 128 + fidx, pol_keep);

        float a0 = gelu_fast(h0.x + htv.x), b0 = gelu_fast(h0.y + htv.y);
        float c0 = gelu_fast(h0.z + htv.z), e0 = gelu_fast(h0.w + htv.w);
        float a1 = gelu_fast(h1.x + htv.x), b1 = gelu_fast(h1.y + htv.y);
        float c1 = gelu_fast(h1.z + htv.z), e1 = gelu_fast(h1.w + htv.w);
        float part0 = fmaf(a0, aw.x, fmaf(b0, aw.y, fmaf(c0, aw.z, e0 * aw.w)));
        float part1 = fmaf(a1, aw.x, fmaf(b1, aw.y, fmaf(c1, aw.z, e1 * aw.w)));
        #pragma unroll
        for (int o = 16; o > 0; o >>= 1) {
            part0 += __shfl_xor_sync(0xffffffffu, part0, o);
            part1 += __shfl_xor_sync(0xffffffffu, part1, o);
        }
        float nm = fmaxf(m, part0);
        float gm = __expf(m - nm);
        float ex = __expf(part0 - nm);
        d = fmaf(d, gm, ex);
        acc = fmaf(acc, gm, msg0 * ex);
        m = nm;
        nm = fmaxf(m, part1);
        gm = __expf(m - nm);
        ex = __expf(part1 - nm);
        d = fmaf(d, gm, ex);
        acc = fmaf(acc, gm, msg1 * ex);
        m = nm;
    }
    if (p < end) {
        int s0 = sorted_src[p];
        float msg0 = ldg_hint1(ms + (size_t)s0 * 128 + fidx, pol_keep);
        float4 h0 = ldg_hint4(hs4 + (size_t)s0 * 128 + fidx, pol_keep);
        float a0 = gelu_fast(h0.x + htv.x), b0 = gelu_fast(h0.y + htv.y);
        float c0 = gelu_fast(h0.z + htv.z), e0 = gelu_fast(h0.w + htv.w);
        float part0 = fmaf(a0, aw.x, fmaf(b0, aw.y, fmaf(c0, aw.z, e0 * aw.w)));
        #pragma unroll
        for (int o = 16; o > 0; o >>= 1)
            part0 += __shfl_xor_sync(0xffffffffu, part0, o);
        float nm = fmaxf(m, part0);
        float gm = __expf(m - nm);
        float ex = __expf(part0 - nm);
        d = fmaf(d, gm, ex);
        acc = fmaf(acc, gm, msg0 * ex);
        m = nm;
    }

    float inv = (end > beg) ? (1.0f / d) : 0.0f;
    stg_stream1(agg + (size_t)tgt * 128 + fidx, acc * inv);
}

// ---------------------------------------------------------------------------
// launch
// ---------------------------------------------------------------------------
extern "C" void kernel_launch(void* const* d_in, const int* in_sizes, int n_in,
                              void* d_out, int out_size) {
    const float* src_f = (const float*)d_in[0];
    const float* tgt_f = (const float*)d_in[1];
    const int*   etgt  = (const int*)d_in[2];
    const int*   esrc  = (const int*)d_in[3];
    const float* Ws    = (const float*)d_in[4];
    const float* bs    = (const float*)d_in[5];
    const float* Wt    = (const float*)d_in[6];
    const float* bt    = (const float*)d_in[7];
    const float* aw    = (const float*)d_in[8];
    const float* Wm    = (const float*)d_in[9];
    const float* bm    = (const float*)d_in[10];
    const float* Wo    = (const float*)d_in[11];
    const float* bo    = (const float*)d_in[12];
    float* out = (float*)d_out;

    int N = in_sizes[0] / EMBED;
    int M = in_sizes[1] / EMBED;
    int E = in_sizes[2];

    float *p_hs, *p_ht, *p_ms, *p_agg;
    int *p_counts, *p_cursor, *p_offsets, *p_ssrc;
    __nv_bfloat16 *p_wsrc, *p_wt, *p_wo;
    cudaGetSymbolAddress((void**)&p_hs, g_hs);
    cudaGetSymbolAddress((void**)&p_ht, g_ht);
    cudaGetSymbolAddress((void**)&p_ms, g_ms);
    cudaGetSymbolAddress((void**)&p_agg, g_agg);
    cudaGetSymbolAddress((void**)&p_counts, g_counts);
    cudaGetSymbolAddress((void**)&p_cursor, g_cursor);
    cudaGetSymbolAddress((void**)&p_offsets, g_offsets);
    cudaGetSymbolAddress((void**)&p_ssrc, g_sorted_src);
    cudaGetSymbolAddress((void**)&p_wsrc, g_wimg_src);
    cudaGetSymbolAddress((void**)&p_wt, g_wimg_t);
    cudaGetSymbolAddress((void**)&p_wo, g_wimg_o);

    cudaFuncSetAttribute(tc_gemm_persist,
                         cudaFuncAttributeMaxDynamicSharedMemorySize, PERSIST_SMEM);

    // 0: weight conversion + counter zeroing
    wconv4z_kernel<<<640, 256>>>(Ws, Wm, Wt, Wo, p_wsrc, p_wt, p_wo,
                                 p_counts, p_cursor, M);
    // 1-3: CSR build
    hist_kernel<<<(E + 255) / 256, 256>>>(etgt, p_counts, E);
    scan_kernel<<<1, 1024>>>(p_counts, p_offsets, M);
    scatter_kernel<<<(E + 255) / 256, 256>>>(etgt, esrc, p_offsets, p_cursor, p_ssrc, E);
    // 4: fused src+tgt GEMMs
    {
        dim3 g(16, 9);
        tc_gemm_persist<<<g, 256, PERSIST_SMEM>>>(src_f, tgt_f, p_agg,
                                                  p_wsrc, p_wt, p_wo,
                                                  bs, bm, bt, bo,
                                                  p_hs, p_ms, p_ht, out,
                                                  N, M, 0);
    }
    // 5: edge attention (capture slot)
    {
        int warps = M * 4;
        int blocks = (warps + 7) / 8;
        edge_attn_kernel<<<blocks, 256>>>(p_ssrc, p_offsets,
                                          (const float4*)p_hs, (const float4*)p_ht,
                                          p_ms, (const float4*)aw,
                                          p_agg, M);
    }
    // 6: output projection
    {
        dim3 g(148, 1);
        tc_gemm_persist<<<g, 256, PERSIST_SMEM>>>(src_f, tgt_f, p_agg,
                                                  p_wsrc, p_wt, p_wo,
                                                  bs, bm, bt, bo,
                                                  p_hs, p_ms, p_ht, out,
                                                  N, M, 9);
    }
}